// round 13
// baseline (speedup 1.0000x reference)
#include <cuda_runtime.h>
#include <cuda_fp16.h>

#define Nn 16384
#define Tt 4
#define Hh 64
#define Ee 262144
#define NT (Nn*Tt)
#define BKT 64                 // bucket stride (max in-degree per type; Poisson(16) -> safe)
#define NEG_SLOPE 0.2f
#define LN_EPS 1e-5f

// -------- scratch (static device globals; no allocation) --------
__device__ __align__(16) __half g_h16[2][NT*Hh];  // fp16 transformed features
__device__ __align__(16) __half g_wh16[4][Hh*Hh]; // fp16 weights (W0s,W0f,W1s,W1f)
__device__ __align__(16) __half g_x16[NT*Hh];     // fp16 copy of layer-0 output
__device__ __align__(16) float g_logits[2][NT];   // leaky(dot(h,a)), layout [N][T]
__device__ __align__(16) float g_xbuf[NT*Hh];     // layer-0 output (fp32)
__device__ int g_cnt[2][Nn];
__device__ int g_bkt[2][Nn*BKT];

__device__ __forceinline__ unsigned h2bits(__half2 h) {
    return *reinterpret_cast<unsigned*>(&h);
}

// ------- single-pass edge bucketing (+ folded W fp32->fp16 prep) -------------
__global__ void k_fill_direct(const int* __restrict__ eis, const int* __restrict__ eif,
                              const float* __restrict__ W0s, const float* __restrict__ W0f,
                              const float* __restrict__ W1s, const float* __restrict__ W1f) {
    // blocks 0..15 also convert the 4 weight matrices (4096 float4 total)
    if (blockIdx.x < 16) {
        int j = blockIdx.x*256 + threadIdx.x;           // 0..4095
        int w = j >> 10, jj = j & 1023;
        const float* srcW = (w == 0) ? W0s : (w == 1) ? W0f : (w == 2) ? W1s : W1f;
        float4 v = ((const float4*)srcW)[jj];
        *(uint2*)&g_wh16[w][jj*4] = make_uint2(
            h2bits(__floats2half2_rn(v.x, v.y)), h2bits(__floats2half2_rn(v.z, v.w)));
    }
    int i = blockIdx.x*blockDim.x + threadIdx.x;        // 0 .. 2*Ee-1
    int src, dst, which;
    if (i < Ee) { which = 0; src = eis[i];      dst = eis[Ee + i]; }
    else        { which = 1; src = eif[i - Ee]; dst = eif[i]; }
    int pos = atomicAdd(&g_cnt[which][dst], 1);
    if (pos < BKT) g_bkt[which][dst*BKT + pos] = src;
}

// ---------------- tensor-core GEMM helpers ----------------
__device__ __forceinline__ void ldsm_x4(unsigned (&r)[4], unsigned addr) {
    asm volatile("ldmatrix.sync.aligned.m8n8.x4.shared.b16 {%0,%1,%2,%3}, [%4];"
        : "=r"(r[0]), "=r"(r[1]), "=r"(r[2]), "=r"(r[3]) : "r"(addr));
}
__device__ __forceinline__ void ldsm_x2t(unsigned (&r)[2], unsigned addr) {
    asm volatile("ldmatrix.sync.aligned.m8n8.x2.trans.shared.b16 {%0,%1}, [%2];"
        : "=r"(r[0]), "=r"(r[1]) : "r"(addr));
}
__device__ __forceinline__ void mma16816(float (&d)[4], const unsigned (&a)[4],
                                         const unsigned (&b)[2]) {
    asm volatile(
        "mma.sync.aligned.m16n8k16.row.col.f32.f16.f16.f32 "
        "{%0,%1,%2,%3},{%4,%5,%6,%7},{%8,%9},{%0,%1,%2,%3};"
        : "+f"(d[0]), "+f"(d[1]), "+f"(d[2]), "+f"(d[3])
        : "r"(a[0]), "r"(a[1]), "r"(a[2]), "r"(a[3]), "r"(b[0]), "r"(b[1]));
}

// ---- fused tensor GEMM: h_s = x@Ws, h_f = x@Wf (fp16 out) + logits ----
// 128-row tile; 256 threads = 8 warps = 4 row-groups x 2 col-groups (m32n32/warp).
// XH: x is pre-converted fp16.
#define XST 72   // smem half-stride (64 + 8 pad)
template<bool XH>
__global__ __launch_bounds__(256, 3) void k_gemm_tc(
        const void* __restrict__ xin,
        const __half* __restrict__ WhS, const float* __restrict__ as_g,
        const __half* __restrict__ WhF, const float* __restrict__ af_g) {
    __shared__ __half xh[128*XST];
    __shared__ __half whS[64*XST];
    __shared__ __half whF[64*XST];
    __shared__ float as_s[64], af_s[64];
    __shared__ float s_pdS[128], s_pdF[128];   // cross-warp logits partials
    const int tid = threadIdx.x;
    const int lane = tid & 31, w = tid >> 5;
    const int wr = w >> 1;           // row group 0..3 (32 rows each)
    const int wc = w & 1;            // col group 0..1 (32 cols each)
    const int rowBase = blockIdx.x * 128;

    if (XH) {
        const uint4* x4 = (const uint4*)((const __half*)xin + rowBase*64);
        #pragma unroll
        for (int i = tid; i < 1024; i += 256) {
            int r = i >> 3, c = (i & 7) * 8;
            *(uint4*)&xh[r*XST + c] = x4[i];
        }
    } else {
        const float4* x4 = (const float4*)((const float*)xin + rowBase*64);
        #pragma unroll
        for (int i = tid; i < 2048; i += 256) {
            int r = i >> 4, c4 = (i & 15) * 4;
            float4 v = x4[i];
            *(uint2*)&xh[r*XST + c4] = make_uint2(
                h2bits(__floats2half2_rn(v.x, v.y)), h2bits(__floats2half2_rn(v.z, v.w)));
        }
    }
    const uint4* Wh4S = (const uint4*)WhS;   // 512 uint4 each
    const uint4* Wh4F = (const uint4*)WhF;
    #pragma unroll
    for (int i = tid; i < 512; i += 256) {
        int r = i >> 3, c = (i & 7) * 8;
        *(uint4*)&whS[r*XST + c] = Wh4S[i];
        *(uint4*)&whF[r*XST + c] = Wh4F[i];
    }
    if (tid < 64) { as_s[tid] = as_g[tid]; af_s[tid] = af_g[tid]; }
    __syncthreads();

    const unsigned xh_s  = (unsigned)__cvta_generic_to_shared(xh);
    const unsigned whS_s = (unsigned)__cvta_generic_to_shared(whS);
    const unsigned whF_s = (unsigned)__cvta_generic_to_shared(whF);

    float accS[2][4][4] = {}, accF[2][4][4] = {};   // [m-tile][n-tile][frag]
    #pragma unroll
    for (int kt = 0; kt < 4; kt++) {
        unsigned a0[4], a1[4];
        int acol = kt*16 + ((lane >> 4) << 3);
        int arow0 = wr*32 + (lane & 15);
        ldsm_x4(a0, xh_s + (unsigned)((arow0*XST + acol) * 2));
        ldsm_x4(a1, xh_s + (unsigned)(((arow0 + 16)*XST + acol) * 2));
        int brow = kt*16 + (lane & 15);
        #pragma unroll
        for (int nt = 0; nt < 4; nt++) {
            unsigned bS[2], bF[2];
            unsigned boff = (unsigned)((brow*XST + wc*32 + nt*8) * 2);
            ldsm_x2t(bS, whS_s + boff);
            ldsm_x2t(bF, whF_s + boff);
            mma16816(accS[0][nt], a0, bS);
            mma16816(accS[1][nt], a1, bS);
            mma16816(accF[0][nt], a0, bF);
            mma16816(accF[1][nt], a1, bF);
        }
    }

    const int g = lane >> 2, tig = lane & 3;
    float pdS[2][2] = {}, pdF[2][2] = {};   // [m-tile][row0/row1]
    #pragma unroll
    for (int mi = 0; mi < 2; mi++) {
        const int row0 = rowBase + wr*32 + mi*16 + g;
        const int row1 = row0 + 8;
        #pragma unroll
        for (int nt = 0; nt < 4; nt++) {
            int c = wc*32 + nt*8 + tig*2;
            *(unsigned*)&g_h16[0][row0*64 + c] = h2bits(__floats2half2_rn(accS[mi][nt][0], accS[mi][nt][1]));
            *(unsigned*)&g_h16[0][row1*64 + c] = h2bits(__floats2half2_rn(accS[mi][nt][2], accS[mi][nt][3]));
            *(unsigned*)&g_h16[1][row0*64 + c] = h2bits(__floats2half2_rn(accF[mi][nt][0], accF[mi][nt][1]));
            *(unsigned*)&g_h16[1][row1*64 + c] = h2bits(__floats2half2_rn(accF[mi][nt][2], accF[mi][nt][3]));
            float a0 = as_s[c], a1 = as_s[c+1];
            float f0 = af_s[c], f1 = af_s[c+1];
            pdS[mi][0] += accS[mi][nt][0]*a0 + accS[mi][nt][1]*a1;
            pdS[mi][1] += accS[mi][nt][2]*a0 + accS[mi][nt][3]*a1;
            pdF[mi][0] += accF[mi][nt][0]*f0 + accF[mi][nt][1]*f1;
            pdF[mi][1] += accF[mi][nt][2]*f0 + accF[mi][nt][3]*f1;
        }
    }
    // reduce across the 4 lanes of each row group
    #pragma unroll
    for (int off = 2; off > 0; off >>= 1) {
        #pragma unroll
        for (int mi = 0; mi < 2; mi++) {
            pdS[mi][0] += __shfl_down_sync(0xffffffffu, pdS[mi][0], off, 4);
            pdS[mi][1] += __shfl_down_sync(0xffffffffu, pdS[mi][1], off, 4);
            pdF[mi][0] += __shfl_down_sync(0xffffffffu, pdF[mi][0], off, 4);
            pdF[mi][1] += __shfl_down_sync(0xffffffffu, pdF[mi][1], off, 4);
        }
    }
    // combine the two col-group warps through smem
    if (wc == 1 && tig == 0) {
        #pragma unroll
        for (int mi = 0; mi < 2; mi++) {
            s_pdS[wr*32 + mi*16 + g]     = pdS[mi][0];
            s_pdS[wr*32 + mi*16 + 8 + g] = pdS[mi][1];
            s_pdF[wr*32 + mi*16 + g]     = pdF[mi][0];
            s_pdF[wr*32 + mi*16 + 8 + g] = pdF[mi][1];
        }
    }
    __syncthreads();
    if (wc == 0 && tig == 0) {
        #pragma unroll
        for (int mi = 0; mi < 2; mi++) {
            int r0l = wr*32 + mi*16 + g;
            int r1l = r0l + 8;
            float vS0 = pdS[mi][0] + s_pdS[r0l];
            float vS1 = pdS[mi][1] + s_pdS[r1l];
            float vF0 = pdF[mi][0] + s_pdF[r0l];
            float vF1 = pdF[mi][1] + s_pdF[r1l];
            g_logits[0][rowBase + r0l] = (vS0 > 0.f) ? vS0 : NEG_SLOPE*vS0;
            g_logits[0][rowBase + r1l] = (vS1 > 0.f) ? vS1 : NEG_SLOPE*vS1;
            g_logits[1][rowBase + r0l] = (vF0 > 0.f) ? vF0 : NEG_SLOPE*vF0;
            g_logits[1][rowBase + r1l] = (vF1 > 0.f) ? vF1 : NEG_SLOPE*vF1;
        }
    }
}

// ------- fully fused: softmax + aggregation + LN (bucket-based) -------------
// blockDim (32,8) = 8 warps -> 4 nodes; warp pair splits the two edge types.
__global__ __launch_bounds__(256) void k_agg_ln(
                         const float* __restrict__ xin,
                         const float* __restrict__ g,
                         const float* __restrict__ b,
                         float* __restrict__ out,
                         __half* __restrict__ out16) {
    __shared__ float s_alpha[8][32][4];
    __shared__ int   s_src[8][32];
    __shared__ float s_part[4][32][9];
    const int ty = threadIdx.y;
    const int slot = ty >> 1;
    const int which = ty & 1;
    const int node = blockIdx.x*4 + slot;
    const int l = threadIdx.x;
    const int t = l >> 3;
    const int c8 = (l & 7) * 8;
    float acc[8] = {};

    const int deg = min(g_cnt[which][node], BKT);
    const int*   __restrict__ srcs = &g_bkt[which][node*BKT];
    const float* __restrict__ lgt  = g_logits[which];
    const uint4* __restrict__ hb4  = (const uint4*)g_h16[which];

    #define ACCUM(V, AL) { \
        float2 f0 = __half22float2(*reinterpret_cast<__half2*>(&(V).x)); \
        float2 f1 = __half22float2(*reinterpret_cast<__half2*>(&(V).y)); \
        float2 f2 = __half22float2(*reinterpret_cast<__half2*>(&(V).z)); \
        float2 f3 = __half22float2(*reinterpret_cast<__half2*>(&(V).w)); \
        acc[0] += (AL)*f0.x; acc[1] += (AL)*f0.y; \
        acc[2] += (AL)*f1.x; acc[3] += (AL)*f1.y; \
        acc[4] += (AL)*f2.x; acc[5] += (AL)*f2.y; \
        acc[6] += (AL)*f3.x; acc[7] += (AL)*f3.y; }

    #define GATHER_LOOP(CNT) { \
        int j = 0; \
        for (; j + 8 <= (CNT); j += 8) { \
            uint4 v0 = hb4[s_src[ty][j+0]*32 + l]; \
            uint4 v1 = hb4[s_src[ty][j+1]*32 + l]; \
            uint4 v2 = hb4[s_src[ty][j+2]*32 + l]; \
            uint4 v3 = hb4[s_src[ty][j+3]*32 + l]; \
            uint4 v4 = hb4[s_src[ty][j+4]*32 + l]; \
            uint4 v5 = hb4[s_src[ty][j+5]*32 + l]; \
            uint4 v6 = hb4[s_src[ty][j+6]*32 + l]; \
            uint4 v7 = hb4[s_src[ty][j+7]*32 + l]; \
            ACCUM(v0, s_alpha[ty][j+0][t]); ACCUM(v1, s_alpha[ty][j+1][t]); \
            ACCUM(v2, s_alpha[ty][j+2][t]); ACCUM(v3, s_alpha[ty][j+3][t]); \
            ACCUM(v4, s_alpha[ty][j+4][t]); ACCUM(v5, s_alpha[ty][j+5][t]); \
            ACCUM(v6, s_alpha[ty][j+6][t]); ACCUM(v7, s_alpha[ty][j+7][t]); \
        } \
        for (; j + 4 <= (CNT); j += 4) { \
            uint4 v0 = hb4[s_src[ty][j+0]*32 + l]; \
            uint4 v1 = hb4[s_src[ty][j+1]*32 + l]; \
            uint4 v2 = hb4[s_src[ty][j+2]*32 + l]; \
            uint4 v3 = hb4[s_src[ty][j+3]*32 + l]; \
            ACCUM(v0, s_alpha[ty][j+0][t]); ACCUM(v1, s_alpha[ty][j+1][t]); \
            ACCUM(v2, s_alpha[ty][j+2][t]); ACCUM(v3, s_alpha[ty][j+3][t]); \
        } \
        for (; j < (CNT); j++) { \
            uint4 v = hb4[s_src[ty][j]*32 + l]; \
            ACCUM(v, s_alpha[ty][j][t]); \
        } }

    if (deg <= 32) {
        // ---- fast path: single logits gather, register softmax ----
        const bool valid = l < deg;
        int s = 0;
        float4 lg = make_float4(-1e30f, -1e30f, -1e30f, -1e30f);
        if (valid) { s = srcs[l]; lg = *(const float4*)&lgt[s*4]; }
        float4 mx = lg;
        #pragma unroll
        for (int off = 16; off > 0; off >>= 1) {
            mx.x = fmaxf(mx.x, __shfl_xor_sync(0xffffffffu, mx.x, off));
            mx.y = fmaxf(mx.y, __shfl_xor_sync(0xffffffffu, mx.y, off));
            mx.z = fmaxf(mx.z, __shfl_xor_sync(0xffffffffu, mx.z, off));
            mx.w = fmaxf(mx.w, __shfl_xor_sync(0xffffffffu, mx.w, off));
        }
        float4 ex = make_float4(0.f, 0.f, 0.f, 0.f);
        if (valid) {
            ex.x = __expf(lg.x - mx.x); ex.y = __expf(lg.y - mx.y);
            ex.z = __expf(lg.z - mx.z); ex.w = __expf(lg.w - mx.w);
        }
        float4 den = ex;
        #pragma unroll
        for (int off = 16; off > 0; off >>= 1) {
            den.x += __shfl_xor_sync(0xffffffffu, den.x, off);
            den.y += __shfl_xor_sync(0xffffffffu, den.y, off);
            den.z += __shfl_xor_sync(0xffffffffu, den.z, off);
            den.w += __shfl_xor_sync(0xffffffffu, den.w, off);
        }
        float4 rd = make_float4(__frcp_rn(den.x), __frcp_rn(den.y),
                                __frcp_rn(den.z), __frcp_rn(den.w));
        if (valid) {
            s_src[ty][l] = s;
            s_alpha[ty][l][0] = ex.x * rd.x;
            s_alpha[ty][l][1] = ex.y * rd.y;
            s_alpha[ty][l][2] = ex.z * rd.z;
            s_alpha[ty][l][3] = ex.w * rd.w;
        }
        __syncwarp();
        GATHER_LOOP(deg);
    } else {
        // ---- general path (32 < deg <= 64): 3-pass ----
        float4 mx = make_float4(-1e30f, -1e30f, -1e30f, -1e30f);
        for (int p = l; p < deg; p += 32) {
            float4 lg = *(const float4*)&lgt[srcs[p]*4];
            mx.x = fmaxf(mx.x, lg.x); mx.y = fmaxf(mx.y, lg.y);
            mx.z = fmaxf(mx.z, lg.z); mx.w = fmaxf(mx.w, lg.w);
        }
        #pragma unroll
        for (int off = 16; off > 0; off >>= 1) {
            mx.x = fmaxf(mx.x, __shfl_xor_sync(0xffffffffu, mx.x, off));
            mx.y = fmaxf(mx.y, __shfl_xor_sync(0xffffffffu, mx.y, off));
            mx.z = fmaxf(mx.z, __shfl_xor_sync(0xffffffffu, mx.z, off));
            mx.w = fmaxf(mx.w, __shfl_xor_sync(0xffffffffu, mx.w, off));
        }
        float4 den = make_float4(0.f, 0.f, 0.f, 0.f);
        for (int p = l; p < deg; p += 32) {
            float4 lg = *(const float4*)&lgt[srcs[p]*4];
            den.x += __expf(lg.x - mx.x); den.y += __expf(lg.y - mx.y);
            den.z += __expf(lg.z - mx.z); den.w += __expf(lg.w - mx.w);
        }
        #pragma unroll
        for (int off = 16; off > 0; off >>= 1) {
            den.x += __shfl_xor_sync(0xffffffffu, den.x, off);
            den.y += __shfl_xor_sync(0xffffffffu, den.y, off);
            den.z += __shfl_xor_sync(0xffffffffu, den.z, off);
            den.w += __shfl_xor_sync(0xffffffffu, den.w, off);
        }
        float4 rd = make_float4(1.f/den.x, 1.f/den.y, 1.f/den.z, 1.f/den.w);

        for (int base = 0; base < deg; base += 32) {
            int p = base + l;
            if (p < deg) {
                int s = srcs[p];
                float4 lg = *(const float4*)&lgt[s*4];
                s_src[ty][l] = s;
                s_alpha[ty][l][0] = __expf(lg.x - mx.x) * rd.x;
                s_alpha[ty][l][1] = __expf(lg.y - mx.y) * rd.y;
                s_alpha[ty][l][2] = __expf(lg.z - mx.z) * rd.z;
                s_alpha[ty][l][3] = __expf(lg.w - mx.w) * rd.w;
            }
            __syncwarp();
            const int cnt = min(32, deg - base);
            GATHER_LOOP(cnt);
            __syncwarp();
        }
    }

    if (which == 1) {
        #pragma unroll
        for (int i = 0; i < 8; i++) s_part[slot][l][i] = acc[i];
    }
    __syncthreads();
    if (which == 0) {
        #pragma unroll
        for (int i = 0; i < 8; i++) acc[i] += s_part[slot][l][i];

        const int row = node*4 + t;
        float4 xi0 = *(const float4*)&xin[row*64 + c8];
        float4 xi1 = *(const float4*)&xin[row*64 + c8 + 4];
        float v[8];
        v[0] = xi0.x + 0.5f*acc[0]; v[1] = xi0.y + 0.5f*acc[1];
        v[2] = xi0.z + 0.5f*acc[2]; v[3] = xi0.w + 0.5f*acc[3];
        v[4] = xi1.x + 0.5f*acc[4]; v[5] = xi1.y + 0.5f*acc[5];
        v[6] = xi1.z + 0.5f*acc[6]; v[7] = xi1.w + 0.5f*acc[7];
        float s = 0.f, sq = 0.f;
        #pragma unroll
        for (int i = 0; i < 8; i++) { s += v[i]; sq += v[i]*v[i]; }
        #pragma unroll
        for (int off = 4; off > 0; off >>= 1) {
            s  += __shfl_xor_sync(0xffffffffu, s,  off);
            sq += __shfl_xor_sync(0xffffffffu, sq, off);
        }
        float mean = s * (1.f/64.f);
        float var  = sq * (1.f/64.f) - mean*mean;
        float rstd = rsqrtf(var + LN_EPS);
        float4 g0 = *(const float4*)&g[c8];
        float4 g1 = *(const float4*)&g[c8+4];
        float4 b0 = *(const float4*)&b[c8];
        float4 b1 = *(const float4*)&b[c8+4];
        float4 o0, o1;
        o0.x = (v[0]-mean)*rstd*g0.x + b0.x;
        o0.y = (v[1]-mean)*rstd*g0.y + b0.y;
        o0.z = (v[2]-mean)*rstd*g0.z + b0.z;
        o0.w = (v[3]-mean)*rstd*g0.w + b0.w;
        o1.x = (v[4]-mean)*rstd*g1.x + b1.x;
        o1.y = (v[5]-mean)*rstd*g1.y + b1.y;
        o1.z = (v[6]-mean)*rstd*g1.z + b1.z;
        o1.w = (v[7]-mean)*rstd*g1.w + b1.w;
        *(float4*)&out[row*64 + c8]     = o0;
        *(float4*)&out[row*64 + c8 + 4] = o1;
        if (out16) {
            uint4 u;
            u.x = h2bits(__floats2half2_rn(o0.x, o0.y));
            u.y = h2bits(__floats2half2_rn(o0.z, o0.w));
            u.z = h2bits(__floats2half2_rn(o1.x, o1.y));
            u.w = h2bits(__floats2half2_rn(o1.z, o1.w));
            *(uint4*)&out16[row*64 + c8] = u;
        }
    }
}

extern "C" void kernel_launch(void* const* d_in, const int* in_sizes, int n_in,
                              void* d_out, int out_size) {
    const float* pred = (const float*)d_in[0];
    const int*   eis  = (const int*)d_in[1];
    const int*   eif  = (const int*)d_in[2];
    const float* W0s = (const float*)d_in[3];
    const float* a0s = (const float*)d_in[4];
    const float* W0f = (const float*)d_in[5];
    const float* a0f = (const float*)d_in[6];
    const float* g0  = (const float*)d_in[7];
    const float* b0  = (const float*)d_in[8];
    const float* W1s = (const float*)d_in[9];
    const float* a1s = (const float*)d_in[10];
    const float* W1f = (const float*)d_in[11];
    const float* a1f = (const float*)d_in[12];
    const float* g1  = (const float*)d_in[13];
    const float* b1  = (const float*)d_in[14];
    float* out = (float*)d_out;

    float* xbuf = nullptr;
    cudaGetSymbolAddress((void**)&xbuf, g_xbuf);
    int* cntp = nullptr;
    cudaGetSymbolAddress((void**)&cntp, g_cnt);
    __half* whp = nullptr;
    cudaGetSymbolAddress((void**)&whp, g_wh16);
    __half* x16p = nullptr;
    cudaGetSymbolAddress((void**)&x16p, g_x16);

    // edge bucketing (shared by both layers) + W prep, one pass
    cudaMemsetAsync(cntp, 0, 2*Nn*sizeof(int));
    k_fill_direct<<<2*Ee/256, 256>>>(eis, eif, W0s, W0f, W1s, W1f);

    // layer 0
    k_gemm_tc<false><<<NT/128, 256>>>(pred, whp, a0s, whp + Hh*Hh, a0f);
    k_agg_ln<<<Nn/4, dim3(32,8)>>>(pred, g0, b0, xbuf, x16p);

    // layer 1
    k_gemm_tc<true><<<NT/128, 256>>>(x16p, whp + 2*Hh*Hh, a1s, whp + 3*Hh*Hh, a1f);
    k_agg_ln<<<Nn/4, dim3(32,8)>>>(xbuf, g1, b1, out, (__half*)nullptr);
}

// round 14
// speedup vs baseline: 1.0600x; 1.0600x over previous
#include <cuda_runtime.h>
#include <cuda_fp16.h>

#define Nn 16384
#define Tt 4
#define Hh 64
#define Ee 262144
#define NT (Nn*Tt)
#define BKT 64                 // bucket stride (max in-degree per type; Poisson(16) -> safe)
#define NEG_SLOPE 0.2f
#define LN_EPS 1e-5f

// -------- scratch (static device globals; no allocation) --------
__device__ __align__(16) __half g_h16[2][NT*Hh];  // fp16 transformed features
__device__ __align__(16) __half g_wh16[4][Hh*Hh]; // fp16 weights (W0s,W0f,W1s,W1f)
__device__ __align__(16) __half g_x16[NT*Hh];     // fp16 layer-0 output
__device__ __align__(16) float g_logits[2][NT];   // leaky(dot(h,a)), layout [N][T]
__device__ int g_cnt[2][Nn];
__device__ int g_bkt[2][Nn*BKT];

__device__ __forceinline__ unsigned h2bits(__half2 h) {
    return *reinterpret_cast<unsigned*>(&h);
}

// ------- single-pass edge bucketing (+ folded W fp32->fp16 prep) -------------
__global__ void k_fill_direct(const int* __restrict__ eis, const int* __restrict__ eif,
                              const float* __restrict__ W0s, const float* __restrict__ W0f,
                              const float* __restrict__ W1s, const float* __restrict__ W1f) {
    // blocks 0..15 also convert the 4 weight matrices (4096 float4 total)
    if (blockIdx.x < 16) {
        int j = blockIdx.x*256 + threadIdx.x;           // 0..4095
        int w = j >> 10, jj = j & 1023;
        const float* srcW = (w == 0) ? W0s : (w == 1) ? W0f : (w == 2) ? W1s : W1f;
        float4 v = ((const float4*)srcW)[jj];
        *(uint2*)&g_wh16[w][jj*4] = make_uint2(
            h2bits(__floats2half2_rn(v.x, v.y)), h2bits(__floats2half2_rn(v.z, v.w)));
    }
    int i = blockIdx.x*blockDim.x + threadIdx.x;        // 0 .. 2*Ee-1
    int src, dst, which;
    if (i < Ee) { which = 0; src = eis[i];      dst = eis[Ee + i]; }
    else        { which = 1; src = eif[i - Ee]; dst = eif[i]; }
    int pos = atomicAdd(&g_cnt[which][dst], 1);
    if (pos < BKT) g_bkt[which][dst*BKT + pos] = src;
}

// ---------------- tensor-core GEMM helpers ----------------
__device__ __forceinline__ void ldsm_x4(unsigned (&r)[4], unsigned addr) {
    asm volatile("ldmatrix.sync.aligned.m8n8.x4.shared.b16 {%0,%1,%2,%3}, [%4];"
        : "=r"(r[0]), "=r"(r[1]), "=r"(r[2]), "=r"(r[3]) : "r"(addr));
}
__device__ __forceinline__ void ldsm_x2t(unsigned (&r)[2], unsigned addr) {
    asm volatile("ldmatrix.sync.aligned.m8n8.x2.trans.shared.b16 {%0,%1}, [%2];"
        : "=r"(r[0]), "=r"(r[1]) : "r"(addr));
}
__device__ __forceinline__ void mma16816(float (&d)[4], const unsigned (&a)[4],
                                         const unsigned (&b)[2]) {
    asm volatile(
        "mma.sync.aligned.m16n8k16.row.col.f32.f16.f16.f32 "
        "{%0,%1,%2,%3},{%4,%5,%6,%7},{%8,%9},{%0,%1,%2,%3};"
        : "+f"(d[0]), "+f"(d[1]), "+f"(d[2]), "+f"(d[3])
        : "r"(a[0]), "r"(a[1]), "r"(a[2]), "r"(a[3]), "r"(b[0]), "r"(b[1]));
}

// ---- fused tensor GEMM: h_s = x@Ws, h_f = x@Wf (fp16 out) + logits ----
// 128-row tile; 256 threads = 8 warps (m16n64/warp). XH: x is pre-converted fp16.
#define XST 72   // smem half-stride (64 + 8 pad)
template<bool XH>
__global__ __launch_bounds__(256) void k_gemm_tc(
        const void* __restrict__ xin,
        const __half* __restrict__ WhS, const float* __restrict__ as_g,
        const __half* __restrict__ WhF, const float* __restrict__ af_g) {
    __shared__ __half xh[128*XST];
    __shared__ __half whS[64*XST];
    __shared__ __half whF[64*XST];
    __shared__ float as_s[64], af_s[64];
    const int tid = threadIdx.x;
    const int lane = tid & 31, w = tid >> 5;
    const int rowBase = blockIdx.x * 128;

    if (XH) {
        const uint4* x4 = (const uint4*)((const __half*)xin + rowBase*64);
        #pragma unroll
        for (int i = tid; i < 1024; i += 256) {
            int r = i >> 3, c = (i & 7) * 8;
            *(uint4*)&xh[r*XST + c] = x4[i];
        }
    } else {
        const float4* x4 = (const float4*)((const float*)xin + rowBase*64);
        #pragma unroll
        for (int i = tid; i < 2048; i += 256) {
            int r = i >> 4, c4 = (i & 15) * 4;
            float4 v = x4[i];
            *(uint2*)&xh[r*XST + c4] = make_uint2(
                h2bits(__floats2half2_rn(v.x, v.y)), h2bits(__floats2half2_rn(v.z, v.w)));
        }
    }
    const uint4* Wh4S = (const uint4*)WhS;   // 512 uint4 each
    const uint4* Wh4F = (const uint4*)WhF;
    #pragma unroll
    for (int i = tid; i < 512; i += 256) {
        int r = i >> 3, c = (i & 7) * 8;
        *(uint4*)&whS[r*XST + c] = Wh4S[i];
        *(uint4*)&whF[r*XST + c] = Wh4F[i];
    }
    if (tid < 64) { as_s[tid] = as_g[tid]; af_s[tid] = af_g[tid]; }
    __syncthreads();

    const unsigned xh_s  = (unsigned)__cvta_generic_to_shared(xh);
    const unsigned whS_s = (unsigned)__cvta_generic_to_shared(whS);
    const unsigned whF_s = (unsigned)__cvta_generic_to_shared(whF);

    float accS[8][4] = {}, accF[8][4] = {};
    #pragma unroll
    for (int kt = 0; kt < 4; kt++) {
        unsigned afrag[4];
        int arow = w*16 + (lane & 15);
        int acol = kt*16 + ((lane >> 4) << 3);
        ldsm_x4(afrag, xh_s + (unsigned)((arow*XST + acol) * 2));
        int brow = kt*16 + (lane & 15);
        #pragma unroll
        for (int nt = 0; nt < 8; nt++) {
            unsigned bS[2], bF[2];
            ldsm_x2t(bS, whS_s + (unsigned)((brow*XST + nt*8) * 2));
            ldsm_x2t(bF, whF_s + (unsigned)((brow*XST + nt*8) * 2));
            mma16816(accS[nt], afrag, bS);
            mma16816(accF[nt], afrag, bF);
        }
    }

    const int g = lane >> 2, tig = lane & 3;
    const int row0 = rowBase + w*16 + g;
    const int row1 = row0 + 8;
    float pS0 = 0.f, pS1 = 0.f, pF0 = 0.f, pF1 = 0.f;
    #pragma unroll
    for (int nt = 0; nt < 8; nt++) {
        int c = nt*8 + tig*2;
        *(unsigned*)&g_h16[0][row0*64 + c] = h2bits(__floats2half2_rn(accS[nt][0], accS[nt][1]));
        *(unsigned*)&g_h16[0][row1*64 + c] = h2bits(__floats2half2_rn(accS[nt][2], accS[nt][3]));
        *(unsigned*)&g_h16[1][row0*64 + c] = h2bits(__floats2half2_rn(accF[nt][0], accF[nt][1]));
        *(unsigned*)&g_h16[1][row1*64 + c] = h2bits(__floats2half2_rn(accF[nt][2], accF[nt][3]));
        float a0 = as_s[c], a1 = as_s[c+1];
        float f0 = af_s[c], f1 = af_s[c+1];
        pS0 += accS[nt][0]*a0 + accS[nt][1]*a1;
        pS1 += accS[nt][2]*a0 + accS[nt][3]*a1;
        pF0 += accF[nt][0]*f0 + accF[nt][1]*f1;
        pF1 += accF[nt][2]*f0 + accF[nt][3]*f1;
    }
    #pragma unroll
    for (int off = 2; off > 0; off >>= 1) {
        pS0 += __shfl_down_sync(0xffffffffu, pS0, off, 4);
        pS1 += __shfl_down_sync(0xffffffffu, pS1, off, 4);
        pF0 += __shfl_down_sync(0xffffffffu, pF0, off, 4);
        pF1 += __shfl_down_sync(0xffffffffu, pF1, off, 4);
    }
    if (tig == 0) {
        g_logits[0][row0] = (pS0 > 0.f) ? pS0 : NEG_SLOPE*pS0;
        g_logits[0][row1] = (pS1 > 0.f) ? pS1 : NEG_SLOPE*pS1;
        g_logits[1][row0] = (pF0 > 0.f) ? pF0 : NEG_SLOPE*pF0;
        g_logits[1][row1] = (pF1 > 0.f) ? pF1 : NEG_SLOPE*pF1;
    }
}

// ------- fully fused: softmax + aggregation + LN (bucket-based) -------------
// blockDim (32,8) = 8 warps -> 4 nodes; warp pair splits the two edge types.
// XH: residual input x is fp16 (g_x16). OUT32: write fp32 output. OUT16: write fp16.
template<bool XH, bool OUT32, bool OUT16>
__global__ __launch_bounds__(256) void k_agg_ln(
                         const void* __restrict__ xin,
                         const float* __restrict__ g,
                         const float* __restrict__ b,
                         float* __restrict__ out,
                         __half* __restrict__ out16) {
    __shared__ float s_alpha[8][32][4];
    __shared__ int   s_src[8][32];
    __shared__ float s_part[4][32][9];
    const int ty = threadIdx.y;
    const int slot = ty >> 1;
    const int which = ty & 1;
    const int node = blockIdx.x*4 + slot;
    const int l = threadIdx.x;
    const int t = l >> 3;
    const int c8 = (l & 7) * 8;
    float acc[8] = {};

    const int deg = min(g_cnt[which][node], BKT);
    const int*   __restrict__ srcs = &g_bkt[which][node*BKT];
    const float* __restrict__ lgt  = g_logits[which];
    const uint4* __restrict__ hb4  = (const uint4*)g_h16[which];

    #define ACCUM(V, AL) { \
        float2 f0 = __half22float2(*reinterpret_cast<__half2*>(&(V).x)); \
        float2 f1 = __half22float2(*reinterpret_cast<__half2*>(&(V).y)); \
        float2 f2 = __half22float2(*reinterpret_cast<__half2*>(&(V).z)); \
        float2 f3 = __half22float2(*reinterpret_cast<__half2*>(&(V).w)); \
        acc[0] += (AL)*f0.x; acc[1] += (AL)*f0.y; \
        acc[2] += (AL)*f1.x; acc[3] += (AL)*f1.y; \
        acc[4] += (AL)*f2.x; acc[5] += (AL)*f2.y; \
        acc[6] += (AL)*f3.x; acc[7] += (AL)*f3.y; }

    #define GATHER_LOOP(CNT) { \
        int j = 0; \
        for (; j + 8 <= (CNT); j += 8) { \
            uint4 v0 = hb4[s_src[ty][j+0]*32 + l]; \
            uint4 v1 = hb4[s_src[ty][j+1]*32 + l]; \
            uint4 v2 = hb4[s_src[ty][j+2]*32 + l]; \
            uint4 v3 = hb4[s_src[ty][j+3]*32 + l]; \
            uint4 v4 = hb4[s_src[ty][j+4]*32 + l]; \
            uint4 v5 = hb4[s_src[ty][j+5]*32 + l]; \
            uint4 v6 = hb4[s_src[ty][j+6]*32 + l]; \
            uint4 v7 = hb4[s_src[ty][j+7]*32 + l]; \
            ACCUM(v0, s_alpha[ty][j+0][t]); ACCUM(v1, s_alpha[ty][j+1][t]); \
            ACCUM(v2, s_alpha[ty][j+2][t]); ACCUM(v3, s_alpha[ty][j+3][t]); \
            ACCUM(v4, s_alpha[ty][j+4][t]); ACCUM(v5, s_alpha[ty][j+5][t]); \
            ACCUM(v6, s_alpha[ty][j+6][t]); ACCUM(v7, s_alpha[ty][j+7][t]); \
        } \
        for (; j + 4 <= (CNT); j += 4) { \
            uint4 v0 = hb4[s_src[ty][j+0]*32 + l]; \
            uint4 v1 = hb4[s_src[ty][j+1]*32 + l]; \
            uint4 v2 = hb4[s_src[ty][j+2]*32 + l]; \
            uint4 v3 = hb4[s_src[ty][j+3]*32 + l]; \
            ACCUM(v0, s_alpha[ty][j+0][t]); ACCUM(v1, s_alpha[ty][j+1][t]); \
            ACCUM(v2, s_alpha[ty][j+2][t]); ACCUM(v3, s_alpha[ty][j+3][t]); \
        } \
        for (; j < (CNT); j++) { \
            uint4 v = hb4[s_src[ty][j]*32 + l]; \
            ACCUM(v, s_alpha[ty][j][t]); \
        } }

    if (deg <= 32) {
        // ---- fast path: single logits gather, register softmax ----
        const bool valid = l < deg;
        int s = 0;
        float4 lg = make_float4(-1e30f, -1e30f, -1e30f, -1e30f);
        if (valid) { s = srcs[l]; lg = *(const float4*)&lgt[s*4]; }
        float4 mx = lg;
        #pragma unroll
        for (int off = 16; off > 0; off >>= 1) {
            mx.x = fmaxf(mx.x, __shfl_xor_sync(0xffffffffu, mx.x, off));
            mx.y = fmaxf(mx.y, __shfl_xor_sync(0xffffffffu, mx.y, off));
            mx.z = fmaxf(mx.z, __shfl_xor_sync(0xffffffffu, mx.z, off));
            mx.w = fmaxf(mx.w, __shfl_xor_sync(0xffffffffu, mx.w, off));
        }
        float4 ex = make_float4(0.f, 0.f, 0.f, 0.f);
        if (valid) {
            ex.x = __expf(lg.x - mx.x); ex.y = __expf(lg.y - mx.y);
            ex.z = __expf(lg.z - mx.z); ex.w = __expf(lg.w - mx.w);
        }
        float4 den = ex;
        #pragma unroll
        for (int off = 16; off > 0; off >>= 1) {
            den.x += __shfl_xor_sync(0xffffffffu, den.x, off);
            den.y += __shfl_xor_sync(0xffffffffu, den.y, off);
            den.z += __shfl_xor_sync(0xffffffffu, den.z, off);
            den.w += __shfl_xor_sync(0xffffffffu, den.w, off);
        }
        float4 rd = make_float4(__frcp_rn(den.x), __frcp_rn(den.y),
                                __frcp_rn(den.z), __frcp_rn(den.w));
        if (valid) {
            s_src[ty][l] = s;
            s_alpha[ty][l][0] = ex.x * rd.x;
            s_alpha[ty][l][1] = ex.y * rd.y;
            s_alpha[ty][l][2] = ex.z * rd.z;
            s_alpha[ty][l][3] = ex.w * rd.w;
        }
        __syncwarp();
        GATHER_LOOP(deg);
    } else {
        // ---- general path (32 < deg <= 64): 3-pass ----
        float4 mx = make_float4(-1e30f, -1e30f, -1e30f, -1e30f);
        for (int p = l; p < deg; p += 32) {
            float4 lg = *(const float4*)&lgt[srcs[p]*4];
            mx.x = fmaxf(mx.x, lg.x); mx.y = fmaxf(mx.y, lg.y);
            mx.z = fmaxf(mx.z, lg.z); mx.w = fmaxf(mx.w, lg.w);
        }
        #pragma unroll
        for (int off = 16; off > 0; off >>= 1) {
            mx.x = fmaxf(mx.x, __shfl_xor_sync(0xffffffffu, mx.x, off));
            mx.y = fmaxf(mx.y, __shfl_xor_sync(0xffffffffu, mx.y, off));
            mx.z = fmaxf(mx.z, __shfl_xor_sync(0xffffffffu, mx.z, off));
            mx.w = fmaxf(mx.w, __shfl_xor_sync(0xffffffffu, mx.w, off));
        }
        float4 den = make_float4(0.f, 0.f, 0.f, 0.f);
        for (int p = l; p < deg; p += 32) {
            float4 lg = *(const float4*)&lgt[srcs[p]*4];
            den.x += __expf(lg.x - mx.x); den.y += __expf(lg.y - mx.y);
            den.z += __expf(lg.z - mx.z); den.w += __expf(lg.w - mx.w);
        }
        #pragma unroll
        for (int off = 16; off > 0; off >>= 1) {
            den.x += __shfl_xor_sync(0xffffffffu, den.x, off);
            den.y += __shfl_xor_sync(0xffffffffu, den.y, off);
            den.z += __shfl_xor_sync(0xffffffffu, den.z, off);
            den.w += __shfl_xor_sync(0xffffffffu, den.w, off);
        }
        float4 rd = make_float4(1.f/den.x, 1.f/den.y, 1.f/den.z, 1.f/den.w);

        for (int base = 0; base < deg; base += 32) {
            int p = base + l;
            if (p < deg) {
                int s = srcs[p];
                float4 lg = *(const float4*)&lgt[s*4];
                s_src[ty][l] = s;
                s_alpha[ty][l][0] = __expf(lg.x - mx.x) * rd.x;
                s_alpha[ty][l][1] = __expf(lg.y - mx.y) * rd.y;
                s_alpha[ty][l][2] = __expf(lg.z - mx.z) * rd.z;
                s_alpha[ty][l][3] = __expf(lg.w - mx.w) * rd.w;
            }
            __syncwarp();
            const int cnt = min(32, deg - base);
            GATHER_LOOP(cnt);
            __syncwarp();
        }
    }

    if (which == 1) {
        #pragma unroll
        for (int i = 0; i < 8; i++) s_part[slot][l][i] = acc[i];
    }
    __syncthreads();
    if (which == 0) {
        #pragma unroll
        for (int i = 0; i < 8; i++) acc[i] += s_part[slot][l][i];

        const int row = node*4 + t;
        float xi[8];
        if (XH) {
            uint4 u = *(const uint4*)((const __half*)xin + row*64 + c8);
            float2 f0 = __half22float2(*reinterpret_cast<__half2*>(&u.x));
            float2 f1 = __half22float2(*reinterpret_cast<__half2*>(&u.y));
            float2 f2 = __half22float2(*reinterpret_cast<__half2*>(&u.z));
            float2 f3 = __half22float2(*reinterpret_cast<__half2*>(&u.w));
            xi[0]=f0.x; xi[1]=f0.y; xi[2]=f1.x; xi[3]=f1.y;
            xi[4]=f2.x; xi[5]=f2.y; xi[6]=f3.x; xi[7]=f3.y;
        } else {
            float4 xi0 = *(const float4*)((const float*)xin + row*64 + c8);
            float4 xi1 = *(const float4*)((const float*)xin + row*64 + c8 + 4);
            xi[0]=xi0.x; xi[1]=xi0.y; xi[2]=xi0.z; xi[3]=xi0.w;
            xi[4]=xi1.x; xi[5]=xi1.y; xi[6]=xi1.z; xi[7]=xi1.w;
        }
        float v[8];
        #pragma unroll
        for (int i = 0; i < 8; i++) v[i] = xi[i] + 0.5f*acc[i];
        float s = 0.f, sq = 0.f;
        #pragma unroll
        for (int i = 0; i < 8; i++) { s += v[i]; sq += v[i]*v[i]; }
        #pragma unroll
        for (int off = 4; off > 0; off >>= 1) {
            s  += __shfl_xor_sync(0xffffffffu, s,  off);
            sq += __shfl_xor_sync(0xffffffffu, sq, off);
        }
        float mean = s * (1.f/64.f);
        float var  = sq * (1.f/64.f) - mean*mean;
        float rstd = rsqrtf(var + LN_EPS);
        float4 g0 = *(const float4*)&g[c8];
        float4 g1 = *(const float4*)&g[c8+4];
        float4 b0 = *(const float4*)&b[c8];
        float4 b1 = *(const float4*)&b[c8+4];
        float o[8];
        o[0] = (v[0]-mean)*rstd*g0.x + b0.x;
        o[1] = (v[1]-mean)*rstd*g0.y + b0.y;
        o[2] = (v[2]-mean)*rstd*g0.z + b0.z;
        o[3] = (v[3]-mean)*rstd*g0.w + b0.w;
        o[4] = (v[4]-mean)*rstd*g1.x + b1.x;
        o[5] = (v[5]-mean)*rstd*g1.y + b1.y;
        o[6] = (v[6]-mean)*rstd*g1.z + b1.z;
        o[7] = (v[7]-mean)*rstd*g1.w + b1.w;
        if (OUT32) {
            *(float4*)&out[row*64 + c8]     = make_float4(o[0], o[1], o[2], o[3]);
            *(float4*)&out[row*64 + c8 + 4] = make_float4(o[4], o[5], o[6], o[7]);
        }
        if (OUT16) {
            uint4 u;
            u.x = h2bits(__floats2half2_rn(o[0], o[1]));
            u.y = h2bits(__floats2half2_rn(o[2], o[3]));
            u.z = h2bits(__floats2half2_rn(o[4], o[5]));
            u.w = h2bits(__floats2half2_rn(o[6], o[7]));
            *(uint4*)&out16[row*64 + c8] = u;
        }
    }
}

extern "C" void kernel_launch(void* const* d_in, const int* in_sizes, int n_in,
                              void* d_out, int out_size) {
    const float* pred = (const float*)d_in[0];
    const int*   eis  = (const int*)d_in[1];
    const int*   eif  = (const int*)d_in[2];
    const float* W0s = (const float*)d_in[3];
    const float* a0s = (const float*)d_in[4];
    const float* W0f = (const float*)d_in[5];
    const float* a0f = (const float*)d_in[6];
    const float* g0  = (const float*)d_in[7];
    const float* b0  = (const float*)d_in[8];
    const float* W1s = (const float*)d_in[9];
    const float* a1s = (const float*)d_in[10];
    const float* W1f = (const float*)d_in[11];
    const float* a1f = (const float*)d_in[12];
    const float* g1  = (const float*)d_in[13];
    const float* b1  = (const float*)d_in[14];
    float* out = (float*)d_out;

    int* cntp = nullptr;
    cudaGetSymbolAddress((void**)&cntp, g_cnt);
    __half* whp = nullptr;
    cudaGetSymbolAddress((void**)&whp, g_wh16);
    __half* x16p = nullptr;
    cudaGetSymbolAddress((void**)&x16p, g_x16);

    // edge bucketing (shared by both layers) + W prep, one pass
    cudaMemsetAsync(cntp, 0, 2*Nn*sizeof(int));
    k_fill_direct<<<2*Ee/256, 256>>>(eis, eif, W0s, W0f, W1s, W1f);

    // layer 0: fp32 input, fp16 output only
    k_gemm_tc<false><<<NT/128, 256>>>(pred, whp, a0s, whp + Hh*Hh, a0f);
    k_agg_ln<false, false, true><<<Nn/4, dim3(32,8)>>>(pred, g0, b0, nullptr, x16p);

    // layer 1: fp16 input, fp32 output
    k_gemm_tc<true><<<NT/128, 256>>>(x16p, whp + 2*Hh*Hh, a1s, whp + 3*Hh*Hh, a1f);
    k_agg_ln<true, true, false><<<Nn/4, dim3(32,8)>>>(x16p, g1, b1, out, nullptr);
}